// round 15
// baseline (speedup 1.0000x reference)
#include <cuda_runtime.h>

// DecorrelatedReNorm forward collapses algebraically:
//   W @ W_inv == I  =>  out = (X - running_mean) @ running_W
// Fused kernel: blocks 0..7 (wave-1 guaranteed) compute rmW = rm @ rW and
// per-64-row zero-flags of E = running_W - I; last ticket block folds the 8
// partials and releases. All blocks spin BEFORE loading X (nothing held across
// the spin). E == 0 (actual buffers) -> pure stream out = X - rmW via 256-bit
// ld/st; dense fallback otherwise. NO per-block completion ticket (it
// serialized block retirement and cost ~8us of wave bubbles in R6/R10/R14);
// instead a trailing 1-warp reset node clears the release flag for the next
// graph replay.

#define CFEAT 512
#define TB    64
#define NBT   (CFEAT / TB)        // 8
#define PBLK  8                   // prep blocks (64 rows of rW each)
#define BLK   256
#define AGRID 16384               // NV8 / (2 * BLK); NV8 = 8,388,608 float8
#define STR8  4194304             // AGRID * BLK, float8 units

__device__ __align__(16) float g_partial[PBLK][CFEAT];
__device__ int                 g_flagmask[NBT];   // [cb]: jb bitmask of E!=0
__device__ int                 g_any;
__device__ __align__(32) float g_rmW[CFEAT];
__device__ int                 g_cnt;             // prep fold ticket
__device__ int                 g_release;         // set by fold; reset node clears

// 256-bit vector load/store helpers (sm_100+).
__device__ __forceinline__ void ldg256_cs(const float* p, float* v) {
    asm volatile("ld.global.cs.v8.f32 {%0,%1,%2,%3,%4,%5,%6,%7}, [%8];"
                 : "=f"(v[0]), "=f"(v[1]), "=f"(v[2]), "=f"(v[3]),
                   "=f"(v[4]), "=f"(v[5]), "=f"(v[6]), "=f"(v[7])
                 : "l"(p));
}
__device__ __forceinline__ void stg256_cs(float* p, const float* v) {
    asm volatile("st.global.cs.v8.f32 [%0], {%1,%2,%3,%4,%5,%6,%7,%8};"
                 :: "l"(p), "f"(v[0]), "f"(v[1]), "f"(v[2]), "f"(v[3]),
                    "f"(v[4]), "f"(v[5]), "f"(v[6]), "f"(v[7])
                 : "memory");
}

__global__ void __launch_bounds__(BLK) fused_kernel(const float* __restrict__ X,
                                                    const float* __restrict__ rm,
                                                    const float* __restrict__ rW,
                                                    float* __restrict__ out) {
    const int b = blockIdx.x;
    const int t = threadIdx.x;

    if (b < PBLK) {
        // ---- prep: block b owns rows [64b, 64b+64) == flag row-block b ----
        int j4 = t & 127;            // float4 column 0..127
        int g  = t >> 7;             // row subgroup 0..1 (32 rows each)
        int j  = j4 * 4;
        int jb = j >> 6;
        int c0 = b * TB + g * 32;

        __shared__ float4 sh[128];
        __shared__ int    shmask;
        __shared__ int    is_last;
        if (t == 0) shmask = 0;
        __syncthreads();

        const float4* W4 = reinterpret_cast<const float4*>(rW);
        float4 acc = make_float4(0.f, 0.f, 0.f, 0.f);
        int diff = 0;
        #pragma unroll 8
        for (int k = 0; k < 32; ++k) {
            int    c   = c0 + k;
            float4 w   = __ldg(&W4[c * (CFEAT / 4) + j4]);
            float  rmc = __ldg(&rm[c]);
            acc.x += rmc * w.x;  acc.y += rmc * w.y;
            acc.z += rmc * w.z;  acc.w += rmc * w.w;
            diff |= (w.x != ((c == j + 0) ? 1.0f : 0.0f));
            diff |= (w.y != ((c == j + 1) ? 1.0f : 0.0f));
            diff |= (w.z != ((c == j + 2) ? 1.0f : 0.0f));
            diff |= (w.w != ((c == j + 3) ? 1.0f : 0.0f));
        }
        if (g == 1) sh[j4] = acc;
        if (diff) atomicOr(&shmask, 1 << jb);   // bitwise: order-independent
        __syncthreads();
        if (g == 0) {
            float4 o = sh[j4];
            acc.x += o.x;  acc.y += o.y;  acc.z += o.z;  acc.w += o.w;
            reinterpret_cast<float4*>(g_partial[b])[j4] = acc;
        }
        if (t == 0) g_flagmask[b] = shmask;     // block b IS flag row-block b
        __threadfence();
        __syncthreads();
        if (t == 0) is_last = (atomicAdd(&g_cnt, 1) == PBLK - 1);
        __syncthreads();

        if (is_last) {               // fold 8 partials + 8 flags, then release
            __threadfence();
            #pragma unroll
            for (int h = 0; h < 2; ++h) {
                int jj = t + h * BLK;
                float s = 0.0f;
                #pragma unroll
                for (int p = 0; p < PBLK; ++p) s += g_partial[p][jj];
                g_rmW[jj] = s;
            }
            if (t == 0) {
                int a = 0;
                #pragma unroll
                for (int p = 0; p < NBT; ++p) a |= g_flagmask[p];
                g_any = (a != 0);
                g_cnt = 0;                            // fold ticket reset
            }
            __syncthreads();
            __threadfence();
            if (t == 0) *(volatile int*)&g_release = 1;
        }
    }

    // ---- wait for prep results (wave-1 only; later waves pass through) ----
    if (t == 0) {
        while (*(volatile int*)&g_release == 0) __nanosleep(32);
    }
    __syncthreads();
    __threadfence();

    // ---- streaming apply: identical shape to the 75.8us standalone kernel --
    const int i0 = b * BLK + t;                  // float8 index (32-bit safe)

    float a[8], c[8];
    ldg256_cs(X + (size_t)i0 * 8, a);
    ldg256_cs(X + ((size_t)i0 + STR8) * 8, c);

    if (!g_any) {
        int j = (i0 & 63) * 8;                   // fixed column of this thread
        float r[8];
        #pragma unroll
        for (int k = 0; k < 8; ++k) r[k] = g_rmW[j + k];
        float o[8];
        #pragma unroll
        for (int k = 0; k < 8; ++k) o[k] = a[k] - r[k];
        stg256_cs(out + (size_t)i0 * 8, o);
        #pragma unroll
        for (int k = 0; k < 8; ++k) o[k] = c[k] - r[k];
        stg256_cs(out + ((size_t)i0 + STR8) * 8, o);
        return;                                  // plain exit: fast retirement
    }

    // General fallback: out = X - rmW + X @ E over flagged 64-row blocks.
    #pragma unroll
    for (int h = 0; h < 2; ++h) {
        long long i8 = (long long)i0 + (long long)h * STR8;
        int       j  = (int)(i8 & 63) * 8;
        long long n  = i8 >> 6;
        int       jb = j / TB;
        const float* xin = (h == 0) ? a : c;

        float o[8];
        #pragma unroll
        for (int k = 0; k < 8; ++k) o[k] = xin[k] - g_rmW[j + k];

        const float* xrow = X + n * CFEAT;
        #pragma unroll
        for (int cb = 0; cb < NBT; ++cb) {
            if (!((__ldg(&g_flagmask[cb]) >> jb) & 1)) continue;
            for (int ci = 0; ci < TB; ++ci) {
                int   cc = cb * TB + ci;
                float xc = xrow[cc];
                #pragma unroll
                for (int k = 0; k < 8; ++k) {
                    float w = rW[cc * CFEAT + j + k];
                    o[k] += xc * (w - ((cc == j + k) ? 1.0f : 0.0f));
                }
            }
        }
        #pragma unroll
        for (int k = 0; k < 8; ++k) out[i8 * 8 + k] = o[k];
    }
}

// Trailing graph node: clears the release flag after ALL fused blocks retired
// (graph edge provides the ordering). Keeps every replay starting from clean
// state without per-block retirement atomics.
__global__ void reset_kernel() {
    if (threadIdx.x == 0) {
        g_release = 0;
        g_cnt     = 0;
    }
}

extern "C" void kernel_launch(void* const* d_in, const int* in_sizes, int n_in,
                              void* d_out, int out_size) {
    const float* X  = (const float*)d_in[0];  // [N, 512]
    const float* rm = (const float*)d_in[1];  // [512]
    const float* rW = (const float*)d_in[2];  // [512, 512]
    float* out = (float*)d_out;

    fused_kernel<<<AGRID, BLK>>>(X, rm, rW, out);
    reset_kernel<<<1, 32>>>();
}

// round 16
// speedup vs baseline: 1.1154x; 1.1154x over previous
#include <cuda_runtime.h>

// DecorrelatedReNorm forward collapses algebraically:
//   W @ W_inv == I  =>  out = (X - running_mean) @ running_W
// running_W = I + E. prep (16 blocks x 1024 threads) computes rmW = rm @ rW
// and per-32-row zero-flags of E in one pass (last-block fold of 16 partials,
// pair-OR of flags into per-64-row masks). apply streams out = X - rmW with
// 256-bit ld/st (2 x v8.f32 per thread, exact cover); dense fallback if E!=0.

#define CFEAT 512
#define TB    64
#define NBT   (CFEAT / TB)        // 8
#define PBLK  16                  // prep blocks (32 rows of rW each)
#define PTHR  1024
#define BLK   256
#define AGRID 16384               // NV8 / (2 * BLK); NV8 = 8,388,608 float8
#define STR8  4194304             // AGRID * BLK, float8 units

__device__ __align__(16) float g_partial[PBLK][CFEAT];
__device__ int                 g_flagpart[PBLK];  // per-block jb bitmask
__device__ int                 g_flagmask[NBT];   // [cb]: jb bitmask of E!=0
__device__ int                 g_any;
__device__ __align__(32) float g_rmW[CFEAT];
__device__ int                 g_cnt;             // zero-init; reset by fold

// 16 blocks; block b owns rows [32b, 32b+32) of rW (half of flag-block b/2).
__global__ void __launch_bounds__(PTHR) prep_kernel(const float* __restrict__ rm,
                                                    const float* __restrict__ rW) {
    int b   = blockIdx.x;        // 0..15
    int t   = threadIdx.x;       // 0..1023
    int j4  = t & 127;           // float4 column 0..127
    int grp = t >> 7;            // row subgroup 0..7 (4 rows each)
    int j   = j4 * 4;
    int jb  = j >> 6;
    int c0  = b * 32 + grp * 4;

    __shared__ float4 sh[8][128];
    __shared__ int    shmask;
    __shared__ int    is_last;
    if (t == 0) shmask = 0;
    __syncthreads();

    const float4* W4 = reinterpret_cast<const float4*>(rW);
    float4 acc = make_float4(0.f, 0.f, 0.f, 0.f);
    int diff = 0;
    #pragma unroll
    for (int k = 0; k < 4; ++k) {
        int    c   = c0 + k;
        float4 w   = __ldg(&W4[c * (CFEAT / 4) + j4]);
        float  rmc = __ldg(&rm[c]);
        acc.x += rmc * w.x;  acc.y += rmc * w.y;
        acc.z += rmc * w.z;  acc.w += rmc * w.w;
        diff |= (w.x != ((c == j + 0) ? 1.0f : 0.0f));
        diff |= (w.y != ((c == j + 1) ? 1.0f : 0.0f));
        diff |= (w.z != ((c == j + 2) ? 1.0f : 0.0f));
        diff |= (w.w != ((c == j + 3) ? 1.0f : 0.0f));
    }
    sh[grp][j4] = acc;
    if (diff) atomicOr(&shmask, 1 << jb);   // bitwise: order-independent
    __syncthreads();

    if (grp == 0) {
        #pragma unroll
        for (int p = 1; p < 8; ++p) {
            float4 o = sh[p][j4];
            acc.x += o.x;  acc.y += o.y;  acc.z += o.z;  acc.w += o.w;
        }
        reinterpret_cast<float4*>(g_partial[b])[j4] = acc;
    }
    if (t == 0) g_flagpart[b] = shmask;
    __threadfence();
    __syncthreads();
    if (t == 0) is_last = (atomicAdd(&g_cnt, 1) == PBLK - 1);
    __syncthreads();

    if (is_last) {               // block-uniform: fold 16 partials + flags
        __threadfence();
        if (t < CFEAT) {
            float s = 0.0f;
            #pragma unroll
            for (int p = 0; p < PBLK; ++p) s += g_partial[p][t];
            g_rmW[t] = s;
        }
        if (t < NBT)             // cb = t: OR the two 32-row halves
            g_flagmask[t] = g_flagpart[2 * t] | g_flagpart[2 * t + 1];
        if (t == 0) {
            int a = 0;
            #pragma unroll
            for (int p = 0; p < PBLK; ++p) a |= g_flagpart[p];
            g_any = (a != 0);
            g_cnt = 0;                       // reset for next graph replay
        }
    }
}

// 256-bit vector load/store helpers (sm_100+).
__device__ __forceinline__ void ldg256_cs(const float* p, float* v) {
    asm volatile("ld.global.cs.v8.f32 {%0,%1,%2,%3,%4,%5,%6,%7}, [%8];"
                 : "=f"(v[0]), "=f"(v[1]), "=f"(v[2]), "=f"(v[3]),
                   "=f"(v[4]), "=f"(v[5]), "=f"(v[6]), "=f"(v[7])
                 : "l"(p));
}
__device__ __forceinline__ void stg256_cs(float* p, const float* v) {
    asm volatile("st.global.cs.v8.f32 [%0], {%1,%2,%3,%4,%5,%6,%7,%8};"
                 :: "l"(p), "f"(v[0]), "f"(v[1]), "f"(v[2]), "f"(v[3]),
                    "f"(v[4]), "f"(v[5]), "f"(v[6]), "f"(v[7])
                 : "memory");
}

// Exactly 2 float8 per thread (AGRID*BLK*2 == NV8). Both loads front-batched.
// Stride is a multiple of 64 float8s -> thread's feature column is fixed.
__global__ void __launch_bounds__(BLK) apply_kernel(const float* __restrict__ X,
                                                    const float* __restrict__ rW,
                                                    float* __restrict__ out) {
    const int i0 = blockIdx.x * BLK + threadIdx.x;   // float8 index (32-bit safe)

    float a[8], c[8];
    ldg256_cs(X + (size_t)i0 * 8, a);
    ldg256_cs(X + ((size_t)i0 + STR8) * 8, c);

    int any = g_any;   // uniform
    if (!any) {
        int j = (i0 & 63) * 8;                       // fixed column of this thread
        float r[8];
        #pragma unroll
        for (int k = 0; k < 8; ++k) r[k] = g_rmW[j + k];
        float o[8];
        #pragma unroll
        for (int k = 0; k < 8; ++k) o[k] = a[k] - r[k];
        stg256_cs(out + (size_t)i0 * 8, o);
        #pragma unroll
        for (int k = 0; k < 8; ++k) o[k] = c[k] - r[k];
        stg256_cs(out + ((size_t)i0 + STR8) * 8, o);
        return;
    }

    // General fallback: out = X - rmW + X @ E over flagged 64-row blocks.
    #pragma unroll
    for (int h = 0; h < 2; ++h) {
        long long i8 = (long long)i0 + (long long)h * STR8;   // float8 index
        int       j  = (int)(i8 & 63) * 8;
        long long n  = i8 >> 6;
        int       jb = j / TB;                                // j..j+7 same block
        const float* xin = (h == 0) ? a : c;

        float o[8];
        #pragma unroll
        for (int k = 0; k < 8; ++k) o[k] = xin[k] - g_rmW[j + k];

        const float* xrow = X + n * CFEAT;
        #pragma unroll
        for (int cb = 0; cb < NBT; ++cb) {
            if (!((__ldg(&g_flagmask[cb]) >> jb) & 1)) continue;
            for (int ci = 0; ci < TB; ++ci) {
                int   cc = cb * TB + ci;
                float xc = xrow[cc];
                #pragma unroll
                for (int k = 0; k < 8; ++k) {
                    float w = rW[cc * CFEAT + j + k];
                    o[k] += xc * (w - ((cc == j + k) ? 1.0f : 0.0f));
                }
            }
        }
        #pragma unroll
        for (int k = 0; k < 8; ++k) out[i8 * 8 + k] = o[k];
    }
}

extern "C" void kernel_launch(void* const* d_in, const int* in_sizes, int n_in,
                              void* d_out, int out_size) {
    const float* X  = (const float*)d_in[0];  // [N, 512]
    const float* rm = (const float*)d_in[1];  // [512]
    const float* rW = (const float*)d_in[2];  // [512, 512]
    float* out = (float*)d_out;

    prep_kernel<<<PBLK, PTHR>>>(rm, rW);
    apply_kernel<<<AGRID, BLK>>>(X, rW, out);
}